// round 15
// baseline (speedup 1.0000x reference)
#include <cuda_runtime.h>
#include <math.h>
#include <stdint.h>

typedef unsigned long long ull;

#define T_STEPS 128
#define BATCH   32
#define NHID    1024
#define NH2     2048
#define NTOK    10000
#define TB      (T_STEPS*BATCH)
#define NB      256          /* persistent blocks (2 per SM) */
#define KSL     4            /* K slices (k-chunk 256) */
#define NT      256          /* threads per persistent block */

__device__ float g_emb[TB*NHID];
__device__ float g_xw0[TB*NH2];
__device__ float g_hidden[TB*NHID];
__device__ ull   g_sp[9][16*NHID];     // packed states: [mp][k]
__device__ ull   g_hp[16*NHID];        // packed h_prev
__device__ ull   g_pC[9][KSL][16][NHID];
__device__ ull   g_pH[9][KSL][16][NHID];
__device__ int   g_cnt2;
__device__ int   g_gen;

__constant__ int c_ein[8] = {0,1,1,1,2,5,3,5};
__constant__ int c_act[8] = {0,1,1,3,2,0,2,1};
__constant__ int c_lu[5][3] = {{0,-1,-1},{1,-1,-1},{2,3,4},{5,7,-1},{6,8,-1}};
__constant__ int c_le[5] = {1,1,3,2,2};

__device__ __forceinline__ float sigf(float x){ return 1.0f/(1.0f+expf(-x)); }
__device__ __forceinline__ float actf(int a, float x){
  if(a==0) return sigf(x);
  if(a==1) return fmaxf(x,0.0f);
  if(a==2) return tanhf(x);
  return x;
}
__device__ __forceinline__ void fma2(ull& d, ull a, ull b){
  asm("fma.rn.f32x2 %0, %1, %2, %0;" : "+l"(d) : "l"(a), "l"(b));
}
__device__ __forceinline__ void add2(ull& d, ull a){
  asm("add.rn.f32x2 %0, %0, %1;" : "+l"(d) : "l"(a));
}
__device__ __forceinline__ ull dupf(float x){
  ull r; asm("mov.b64 %0, {%1, %1};" : "=l"(r) : "r"(__float_as_uint(x))); return r;
}
__device__ __forceinline__ ull packf(float lo, float hi){
  ull r; asm("mov.b64 %0, {%1, %2};" : "=l"(r) : "r"(__float_as_uint(lo)), "r"(__float_as_uint(hi))); return r;
}
__device__ __forceinline__ float lo2(ull v){ return __uint_as_float((unsigned)(v & 0xffffffffull)); }
__device__ __forceinline__ float hi2(ull v){ return __uint_as_float((unsigned)(v >> 32)); }

// grid barrier: generation counter, replay-safe (R6-proven scheme)
__device__ __forceinline__ void gbar(int& bar){
  __threadfence();
  __syncthreads();
  if(threadIdx.x==0){
    bar++;
    const int old = atomicAdd(&g_cnt2,1);
    if(old==NB-1){
      atomicExch(&g_cnt2,0);
      __threadfence();
      atomicExch(&g_gen,bar);
    } else {
      while(*(volatile int*)&g_gen - bar < 0) __nanosleep(16);
    }
    __threadfence();
  }
  __syncthreads();
}

// reduce one unit at (mp,col): sum K-partials + bias/residual, activate, store packed
__device__ __forceinline__ void red_unit(int unit,int mp,int col,int t,float& o0,float& o1){
  float cl=0.f,ch=0.f,hl=0.f,hh=0.f;
  #pragma unroll
  for(int s=0;s<KSL;s++){
    const ull v=g_pC[unit][s][mp][col], w=g_pH[unit][s][mp][col];
    cl+=lo2(v); ch+=hi2(v); hl+=lo2(w); hh+=hi2(w);
  }
  const int m0=2*mp, m1=m0+1;
  if(unit==0){
    const size_t xb=((size_t)t*BATCH)*NH2;
    cl+=__ldg(&g_xw0[xb+(size_t)m0*NH2+col]);
    ch+=__ldg(&g_xw0[xb+(size_t)m1*NH2+col]);
    hl+=__ldg(&g_xw0[xb+(size_t)m0*NH2+NHID+col]);
    hh+=__ldg(&g_xw0[xb+(size_t)m1*NH2+NHID+col]);
    const ull hp=g_hp[mp*NHID+col];
    const float hp0=lo2(hp), hp1=hi2(hp);
    o0=hp0+sigf(cl)*(tanhf(hl)-hp0);
    o1=hp1+sigf(ch)*(tanhf(hh)-hp1);
  } else {
    const int e=unit-1, a=c_act[e];
    const ull spv=g_sp[c_ein[e]][mp*NHID+col];
    const float sp0=lo2(spv), sp1=hi2(spv);
    o0=sp0+sigf(cl)*(actf(a,hl)-sp0);
    o1=sp1+sigf(ch)*(actf(a,hh)-sp1);
  }
  g_sp[unit][mp*NHID+col]=packf(o0,o1);
}

// ---------------- pack h0 into g_hp (one-time) ------------------------------
__global__ void k_pack0(const float* __restrict__ h0in){
  const int i=blockIdx.x*256+threadIdx.x;
  const int mp=i>>10, col=i&1023;
  g_hp[mp*NHID+col]=packf(h0in[(size_t)(2*mp)*NHID+col], h0in[(size_t)(2*mp+1)*NHID+col]);
}

// ---------------- persistent recurrence kernel ------------------------------
// block(256): cp=tid&15 col lane, kg=(tid>>4)&7 k-subgroup(32k), mh=tid>>7 mp-half
// grid(256):  jt=bid&63 j-tile(16 col-pairs), ks=bid>>6 K-slice(256 k)
// 2 blocks per SM: sibling block's warps fill sync/barrier stalls.
// Per-thread inner loop identical to the proven R6 kernel.
__global__ __launch_bounds__(NT,2) void k_rnn(const float* __restrict__ W0,
                                              const float* __restrict__ Ws){
  __shared__ __align__(16) ull ap[256][18];   // 36.9KB: A-stage / reduce buffer
  __shared__ ull rbuf[2][64];
  const int tid=threadIdx.x, bid=blockIdx.x;
  const int cp = tid&15, kg = (tid>>4)&7, mh = tid>>7;
  const int jt = bid&63, ks = bid>>6;
  const int col = jt*16 + cp;
  const int k0  = ks*256;
  const int kb  = kg*32;
  const int mpb = mh*8;
  int bar = *(volatile int*)&g_gen;

  for(int t=0;t<T_STEPS;t++){
    for(int L=0;L<5;L++){
      const int E=c_le[L];
      for(int ii=0;ii<E;ii++){
        const int unit=c_lu[L][ii];
        const ull* __restrict__ Ain = (unit==0)? g_hp : g_sp[c_ein[unit-1]];
        // coalesced packed staging: 4096 ull, 16 per thread
        for(int i=tid;i<4096;i+=NT){
          const int mp=i>>8, k=i&255;
          ap[k][mp]=Ain[mp*NHID + k0 + k];
        }
        __syncthreads();
        const float* __restrict__ wc =
          ((unit==0)? (W0+(size_t)NHID*NH2) : (Ws+(size_t)(unit-1)*NHID*NH2))
          + (size_t)(k0+kb)*NH2 + col;
        const float* __restrict__ wh = wc + NHID;
        ull aC[8], aH[8];
        #pragma unroll
        for(int i=0;i<8;i++){aC[i]=0ull;aH[i]=0ull;}
        float pc[4],ph[4];
        #pragma unroll
        for(int i=0;i<4;i++){pc[i]=__ldg(wc+(size_t)i*NH2); ph[i]=__ldg(wh+(size_t)i*NH2);}
        #pragma unroll 4
        for(int k=0;k<32;k++){
          const int r=k&3;
          float nc=0.f,nh=0.f;
          if(k+4<32){ nc=__ldg(wc+(size_t)(k+4)*NH2); nh=__ldg(wh+(size_t)(k+4)*NH2); }
          const ull dc=dupf(pc[r]), dh=dupf(ph[r]);
          const ulonglong2* apk=(const ulonglong2*)&ap[kb+k][mpb];
          #pragma unroll
          for(int i=0;i<4;i++){
            const ulonglong2 a=apk[i];
            fma2(aC[2*i],a.x,dc); fma2(aC[2*i+1],a.y,dc);
            fma2(aH[2*i],a.x,dh); fma2(aH[2*i+1],a.y,dh);
          }
          pc[r]=nc; ph[r]=nh;
        }
        __syncthreads();
        // tree reduce across 8 kg subgroups -> kg0 (per mh,cp); slot=(kg<<5)+(mh<<4)+cp
        ull* red=&ap[0][0];
        #pragma unroll
        for(int half=4; half>=1; half>>=1){
          if(kg>=half && kg<2*half){
            ull* dst = red + (size_t)(((kg-half)<<5)+(mh<<4)+cp)*17;
            #pragma unroll
            for(int i=0;i<8;i++){ dst[i]=aC[i]; dst[8+i]=aH[i]; }
          }
          __syncthreads();
          if(kg<half){
            const ull* src = red + (size_t)((kg<<5)+(mh<<4)+cp)*17;
            #pragma unroll
            for(int i=0;i<8;i++){ add2(aC[i],src[i]); add2(aH[i],src[8+i]); }
          }
          __syncthreads();
        }
        if(kg==0){
          #pragma unroll
          for(int i=0;i<8;i++){
            g_pC[unit][ks][mpb+i][col]=aC[i];
            g_pH[unit][ks][mpb+i][col]=aH[i];
          }
        }
        __syncthreads();
      }
      gbar(bar);
      // ---- reduce/activate phase: (position, unit-slot) across 256 threads ----
      {
        const int pslot = tid>>6;            // 0..3
        const int ppos  = tid&63;
        const int pos   = bid*64 + ppos;     // 16384 positions
        const int mp=pos>>10, pcol=pos&1023;
        if(pslot<E){
          float o0,o1;
          red_unit(c_lu[L][pslot],mp,pcol,t,o0,o1);
          if(L==4) rbuf[pslot][ppos]=packf(o0,o1);
        }
        if(L==4){
          __syncthreads();
          if(pslot==3){   // hidden[t] = mean(s1..s8); s6,s8 fresh in rbuf
            const ull va=rbuf[0][ppos], vb=rbuf[1][ppos];
            float h0v=lo2(va)+lo2(vb), h1v=hi2(va)+hi2(vb);
            #pragma unroll
            for(int s=1;s<6;s++){
              const ull v=g_sp[s][mp*NHID+pcol];
              h0v+=lo2(v); h1v+=hi2(v);
            }
            { const ull v=g_sp[7][mp*NHID+pcol]; h0v+=lo2(v); h1v+=hi2(v); }
            h0v*=0.125f; h1v*=0.125f;
            const int m0=2*mp;
            g_hidden[(size_t)t*BATCH*NHID+(size_t)m0*NHID+pcol]=h0v;
            g_hidden[(size_t)t*BATCH*NHID+(size_t)(m0+1)*NHID+pcol]=h1v;
            g_hp[mp*NHID+pcol]=packf(h0v,h1v);
          }
        }
      }
      gbar(bar);
    }
  }
}

// ---------------- embedding gather ----------------
__global__ void k_embed(const int* __restrict__ tok, const float* __restrict__ encW){
  const int tb=blockIdx.x, t=tok[tb];
  const float4* s=reinterpret_cast<const float4*>(encW+(size_t)t*NHID);
  float4* d=reinterpret_cast<float4*>(g_emb+(size_t)tb*NHID);
  d[threadIdx.x]=s[threadIdx.x];
}

// ---------------- xw0: emb(4096x1024) @ W0[0:1024,:] (fp32x2, 128x64 tile) --
__global__ void k_xw0f(const float* __restrict__ W0){
  __shared__ float As[16][136];
  __shared__ float Bs[16][68];
  const int tid=threadIdx.x;
  const int m0=blockIdx.y*128, n0=blockIdx.x*64;
  const int mg=tid>>4, ng=tid&15;
  const int m0t=mg<<3, n0t=ng<<2;
  ull acc[4][4];
  #pragma unroll
  for(int p=0;p<4;p++)
    #pragma unroll
    for(int n=0;n<4;n++) acc[p][n]=0ull;
  for(int kk0=0;kk0<NHID;kk0+=16){
    #pragma unroll
    for(int it=0;it<2;it++){
      const int li=tid+(it<<8);
      const int r=li>>2, q=(li&3)<<2;
      const float4 v=*reinterpret_cast<const float4*>(&g_emb[(size_t)(m0+r)*NHID+kk0+q]);
      As[q+0][r]=v.x; As[q+1][r]=v.y; As[q+2][r]=v.z; As[q+3][r]=v.w;
    }
    {
      const int r=tid>>4, q=(tid&15)<<2;
      const float4 v=*reinterpret_cast<const float4*>(&W0[(size_t)(kk0+r)*NH2+n0+q]);
      *reinterpret_cast<float4*>(&Bs[r][q])=v;
    }
    __syncthreads();
    #pragma unroll
    for(int kk=0;kk<16;kk++){
      const ulonglong2 a01=*reinterpret_cast<const ulonglong2*>(&As[kk][m0t]);
      const ulonglong2 a23=*reinterpret_cast<const ulonglong2*>(&As[kk][m0t+4]);
      const float4 b=*reinterpret_cast<const float4*>(&Bs[kk][n0t]);
      const ull b0=dupf(b.x), b1=dupf(b.y), b2=dupf(b.z), b3=dupf(b.w);
      fma2(acc[0][0],a01.x,b0); fma2(acc[0][1],a01.x,b1);
      fma2(acc[0][2],a01.x,b2); fma2(acc[0][3],a01.x,b3);
      fma2(acc[1][0],a01.y,b0); fma2(acc[1][1],a01.y,b1);
      fma2(acc[1][2],a01.y,b2); fma2(acc[1][3],a01.y,b3);
      fma2(acc[2][0],a23.x,b0); fma2(acc[2][1],a23.x,b1);
      fma2(acc[2][2],a23.x,b2); fma2(acc[2][3],a23.x,b3);
      fma2(acc[3][0],a23.y,b0); fma2(acc[3][1],a23.y,b1);
      fma2(acc[3][2],a23.y,b2); fma2(acc[3][3],a23.y,b3);
    }
    __syncthreads();
  }
  #pragma unroll
  for(int p=0;p<4;p++){
    const int m=m0+m0t+(p<<1);
    #pragma unroll
    for(int nn=0;nn<4;nn++){
      const int n_=n0+n0t+nn;
      g_xw0[(size_t)m*NH2+n_]    =lo2(acc[p][nn]);
      g_xw0[(size_t)(m+1)*NH2+n_]=hi2(acc[p][nn]);
    }
  }
}

// ---------------- decoder: logits = hidden @ encW^T + dec_b (128x64 tile) ---
__global__ void k_dec(const float* __restrict__ encW, const float* __restrict__ decb,
                      float* __restrict__ out){
  __shared__ float As[16][136];
  __shared__ float Bs[16][68];
  const int tid=threadIdx.x;
  const int m0=blockIdx.y*128, n0=blockIdx.x*64;
  const int mg=tid>>4, ng=tid&15;
  const int m0t=mg<<3, n0t=ng<<2;
  ull acc[4][4];
  #pragma unroll
  for(int p=0;p<4;p++)
    #pragma unroll
    for(int n=0;n<4;n++) acc[p][n]=0ull;
  for(int kk0=0;kk0<NHID;kk0+=16){
    #pragma unroll
    for(int it=0;it<2;it++){
      const int li=tid+(it<<8);
      const int r=li>>2, q=(li&3)<<2;
      const float4 v=*reinterpret_cast<const float4*>(&g_hidden[(size_t)(m0+r)*NHID+kk0+q]);
      As[q+0][r]=v.x; As[q+1][r]=v.y; As[q+2][r]=v.z; As[q+3][r]=v.w;
    }
    {
      const int r=tid>>2, q=(tid&3)<<2;
      const int n=n0+r;
      float4 v=make_float4(0.f,0.f,0.f,0.f);
      if(n<NTOK) v=*reinterpret_cast<const float4*>(&encW[(size_t)n*NHID+kk0+q]);
      Bs[q+0][r]=v.x; Bs[q+1][r]=v.y; Bs[q+2][r]=v.z; Bs[q+3][r]=v.w;
    }
    __syncthreads();
    #pragma unroll
    for(int kk=0;kk<16;kk++){
      const ulonglong2 a01=*reinterpret_cast<const ulonglong2*>(&As[kk][m0t]);
      const ulonglong2 a23=*reinterpret_cast<const ulonglong2*>(&As[kk][m0t+4]);
      const float4 b=*reinterpret_cast<const float4*>(&Bs[kk][n0t]);
      const ull b0=dupf(b.x), b1=dupf(b.y), b2=dupf(b.z), b3=dupf(b.w);
      fma2(acc[0][0],a01.x,b0); fma2(acc[0][1],a01.x,b1);
      fma2(acc[0][2],a01.x,b2); fma2(acc[0][3],a01.x,b3);
      fma2(acc[1][0],a01.y,b0); fma2(acc[1][1],a01.y,b1);
      fma2(acc[1][2],a01.y,b2); fma2(acc[1][3],a01.y,b3);
      fma2(acc[2][0],a23.x,b0); fma2(acc[2][1],a23.x,b1);
      fma2(acc[2][2],a23.x,b2); fma2(acc[2][3],a23.x,b3);
      fma2(acc[3][0],a23.y,b0); fma2(acc[3][1],a23.y,b1);
      fma2(acc[3][2],a23.y,b2); fma2(acc[3][3],a23.y,b3);
    }
    __syncthreads();
  }
  #pragma unroll
  for(int p=0;p<4;p++){
    const int m=m0+m0t+(p<<1);
    #pragma unroll
    for(int nn=0;nn<4;nn++){
      const int n_=n0+n0t+nn;
      if(n_<NTOK){
        const float bias=decb[n_];
        out[(size_t)m*NTOK+n_]    =lo2(acc[p][nn])+bias;
        out[(size_t)(m+1)*NTOK+n_]=hi2(acc[p][nn])+bias;
      }
    }
  }
}

// ---------------- in-place log_softmax --------------------------------------
__global__ void k_lsm(float* __restrict__ out){
  const int row=blockIdx.x;
  float* p=out+(size_t)row*NTOK;
  __shared__ float red[256];
  float mx=-1e30f;
  for(int i=threadIdx.x;i<NTOK;i+=256) mx=fmaxf(mx,p[i]);
  red[threadIdx.x]=mx; __syncthreads();
  for(int s=128;s>0;s>>=1){
    if(threadIdx.x<s) red[threadIdx.x]=fmaxf(red[threadIdx.x],red[threadIdx.x+s]);
    __syncthreads();
  }
  mx=red[0]; __syncthreads();
  float sum=0.f;
  for(int i=threadIdx.x;i<NTOK;i+=256) sum+=expf(p[i]-mx);
  red[threadIdx.x]=sum; __syncthreads();
  for(int s=128;s>0;s>>=1){
    if(threadIdx.x<s) red[threadIdx.x]+=red[threadIdx.x+s];
    __syncthreads();
  }
  const float lse=mx+logf(red[0]);
  for(int i=threadIdx.x;i<NTOK;i+=256) p[i]=p[i]-lse;
}

__global__ void k_hlast(float* __restrict__ out){
  float4* d=reinterpret_cast<float4*>(out+(size_t)TB*NTOK);
  const float4* s=reinterpret_cast<const float4*>(g_hidden+(size_t)(T_STEPS-1)*BATCH*NHID);
  const int i=blockIdx.x*256+threadIdx.x;
  d[i]=s[i];
}

extern "C" void kernel_launch(void* const* d_in, const int* in_sizes, int n_in,
                              void* d_out, int out_size){
  const int*   tokens=(const int*)  d_in[0];
  const float* h0    =(const float*)d_in[1];
  const float* encW  =(const float*)d_in[2];
  const float* W0    =(const float*)d_in[3];
  const float* Ws    =(const float*)d_in[4];
  const float* decb  =(const float*)d_in[5];
  float* out=(float*)d_out;

  k_embed<<<TB,256>>>(tokens,encW);
  k_pack0<<<64,256>>>(h0);
  k_xw0f<<<dim3(NH2/64,TB/128),256>>>(W0);
  k_rnn<<<NB,NT>>>(W0,Ws);
  k_dec<<<dim3((NTOK+63)/64,TB/128),256>>>(encW,decb,out);
  k_lsm<<<TB,256>>>(out);
  k_hlast<<<(BATCH*NHID/4)/256,256>>>(out);
}

// round 16
// speedup vs baseline: 1.1952x; 1.1952x over previous
#include <cuda_runtime.h>
#include <math.h>
#include <stdint.h>

typedef unsigned long long ull;

#define T_STEPS 128
#define BATCH   32
#define NHID    1024
#define NH2     2048
#define NTOK    10000
#define TB      (T_STEPS*BATCH)
#define NB      128          /* persistent blocks */
#define KSL     4            /* K slices (k-chunk 256) */
#define NT      512          /* threads per persistent block */

__device__ float g_emb[TB*NHID];
__device__ float g_xw0[TB*NH2];
__device__ float g_hidden[TB*NHID];
__device__ ull   g_sp[9][16*NHID];     // packed states: [mp][k]
__device__ ull   g_hp[16*NHID];        // packed h_prev
__device__ ull   g_pC[9][KSL][16][NHID];
__device__ ull   g_pH[9][KSL][16][NHID];
__device__ int   g_cnt2;
__device__ int   g_gen;

__constant__ int c_ein[8] = {0,1,1,1,2,5,3,5};
__constant__ int c_act[8] = {0,1,1,3,2,0,2,1};
__constant__ int c_lu[5][3] = {{0,-1,-1},{1,-1,-1},{2,3,4},{5,7,-1},{6,8,-1}};
__constant__ int c_le[5] = {1,1,3,2,2};

__device__ __forceinline__ float sigf(float x){ return 1.0f/(1.0f+expf(-x)); }
__device__ __forceinline__ float actf(int a, float x){
  if(a==0) return sigf(x);
  if(a==1) return fmaxf(x,0.0f);
  if(a==2) return tanhf(x);
  return x;
}
__device__ __forceinline__ void fma2(ull& d, ull a, ull b){
  asm("fma.rn.f32x2 %0, %1, %2, %0;" : "+l"(d) : "l"(a), "l"(b));
}
__device__ __forceinline__ void add2(ull& d, ull a){
  asm("add.rn.f32x2 %0, %0, %1;" : "+l"(d) : "l"(a));
}
__device__ __forceinline__ ull dupf(float x){
  ull r; asm("mov.b64 %0, {%1, %1};" : "=l"(r) : "r"(__float_as_uint(x))); return r;
}
__device__ __forceinline__ ull packf(float lo, float hi){
  ull r; asm("mov.b64 %0, {%1, %2};" : "=l"(r) : "r"(__float_as_uint(lo)), "r"(__float_as_uint(hi))); return r;
}
__device__ __forceinline__ float lo2(ull v){ return __uint_as_float((unsigned)(v & 0xffffffffull)); }
__device__ __forceinline__ float hi2(ull v){ return __uint_as_float((unsigned)(v >> 32)); }

__device__ __forceinline__ uint32_t f2tf(float f){
  uint32_t t; asm("cvt.rna.tf32.f32 %0, %1;" : "=r"(t) : "f"(f)); return t;
}
__device__ __forceinline__ void mma_tf32(float* d, uint32_t a0,uint32_t a1,uint32_t a2,uint32_t a3,
                                         uint32_t b0,uint32_t b1){
  asm("mma.sync.aligned.m16n8k8.row.col.f32.tf32.tf32.f32 "
      "{%0,%1,%2,%3}, {%4,%5,%6,%7}, {%8,%9}, {%0,%1,%2,%3};"
      : "+f"(d[0]),"+f"(d[1]),"+f"(d[2]),"+f"(d[3])
      : "r"(a0),"r"(a1),"r"(a2),"r"(a3),"r"(b0),"r"(b1));
}

// grid barrier: generation counter, replay-safe (R6-proven scheme)
__device__ __forceinline__ void gbar(int& bar){
  __threadfence();
  __syncthreads();
  if(threadIdx.x==0){
    bar++;
    const int old = atomicAdd(&g_cnt2,1);
    if(old==NB-1){
      atomicExch(&g_cnt2,0);
      __threadfence();
      atomicExch(&g_gen,bar);
    } else {
      while(*(volatile int*)&g_gen - bar < 0) __nanosleep(16);
    }
    __threadfence();
  }
  __syncthreads();
}

// reduce one unit at (mp,col): sum K-partials + bias/residual, activate, store packed
__device__ __forceinline__ void red_unit(int unit,int mp,int col,int t,float& o0,float& o1){
  float cl=0.f,ch=0.f,hl=0.f,hh=0.f;
  #pragma unroll
  for(int s=0;s<KSL;s++){
    const ull v=g_pC[unit][s][mp][col], w=g_pH[unit][s][mp][col];
    cl+=lo2(v); ch+=hi2(v); hl+=lo2(w); hh+=hi2(w);
  }
  const int m0=2*mp, m1=m0+1;
  if(unit==0){
    const size_t xb=((size_t)t*BATCH)*NH2;
    cl+=__ldg(&g_xw0[xb+(size_t)m0*NH2+col]);
    ch+=__ldg(&g_xw0[xb+(size_t)m1*NH2+col]);
    hl+=__ldg(&g_xw0[xb+(size_t)m0*NH2+NHID+col]);
    hh+=__ldg(&g_xw0[xb+(size_t)m1*NH2+NHID+col]);
    const ull hp=g_hp[mp*NHID+col];
    const float hp0=lo2(hp), hp1=hi2(hp);
    o0=hp0+sigf(cl)*(tanhf(hl)-hp0);
    o1=hp1+sigf(ch)*(tanhf(hh)-hp1);
  } else {
    const int e=unit-1, a=c_act[e];
    const ull spv=g_sp[c_ein[e]][mp*NHID+col];
    const float sp0=lo2(spv), sp1=hi2(spv);
    o0=sp0+sigf(cl)*(actf(a,hl)-sp0);
    o1=sp1+sigf(ch)*(actf(a,hh)-sp1);
  }
  g_sp[unit][mp*NHID+col]=packf(o0,o1);
}

// ---------------- pack h0 into g_hp (one-time) ------------------------------
__global__ void k_pack0(const float* __restrict__ h0in){
  const int i=blockIdx.x*256+threadIdx.x;
  const int mp=i>>10, col=i&1023;
  g_hp[mp*NHID+col]=packf(h0in[(size_t)(2*mp)*NHID+col], h0in[(size_t)(2*mp+1)*NHID+col]);
}

// ---------------- persistent recurrence kernel (EXACT R6) -------------------
__global__ __launch_bounds__(NT,1) void k_rnn(const float* __restrict__ W0,
                                              const float* __restrict__ Ws){
  __shared__ __align__(16) ull ap[256][18];
  __shared__ ull rbuf[2][128];
  const int tid=threadIdx.x, bid=blockIdx.x;
  const int cp = tid&31, kg = (tid>>5)&7, mh = tid>>8;
  const int jt = bid&31, ks = bid>>5;
  const int col = jt*32 + cp;
  const int k0  = ks*256;
  const int kb  = kg*32;
  const int mpb = mh*8;
  int bar = *(volatile int*)&g_gen;

  for(int t=0;t<T_STEPS;t++){
    for(int L=0;L<5;L++){
      const int E=c_le[L];
      for(int ii=0;ii<E;ii++){
        const int unit=c_lu[L][ii];
        const ull* __restrict__ Ain = (unit==0)? g_hp : g_sp[c_ein[unit-1]];
        for(int i=tid;i<4096;i+=NT){
          const int mp=i>>8, k=i&255;
          ap[k][mp]=Ain[mp*NHID + k0 + k];
        }
        __syncthreads();
        const float* __restrict__ wc =
          ((unit==0)? (W0+(size_t)NHID*NH2) : (Ws+(size_t)(unit-1)*NHID*NH2))
          + (size_t)(k0+kb)*NH2 + col;
        const float* __restrict__ wh = wc + NHID;
        ull aC[8], aH[8];
        #pragma unroll
        for(int i=0;i<8;i++){aC[i]=0ull;aH[i]=0ull;}
        float pc[4],ph[4];
        #pragma unroll
        for(int i=0;i<4;i++){pc[i]=wc[(size_t)i*NH2]; ph[i]=wh[(size_t)i*NH2];}
        #pragma unroll 4
        for(int k=0;k<32;k++){
          const int r=k&3;
          float nc=0.f,nh=0.f;
          if(k+4<32){ nc=wc[(size_t)(k+4)*NH2]; nh=wh[(size_t)(k+4)*NH2]; }
          const ull dc=dupf(pc[r]), dh=dupf(ph[r]);
          const ulonglong2* apk=(const ulonglong2*)&ap[kb+k][mpb];
          #pragma unroll
          for(int i=0;i<4;i++){
            const ulonglong2 a=apk[i];
            fma2(aC[2*i],a.x,dc); fma2(aC[2*i+1],a.y,dc);
            fma2(aH[2*i],a.x,dh); fma2(aH[2*i+1],a.y,dh);
          }
          pc[r]=nc; ph[r]=nh;
        }
        __syncthreads();
        ull* red=&ap[0][0];
        #pragma unroll
        for(int half=4; half>=1; half>>=1){
          if(kg>=half && kg<2*half){
            ull* dst = red + (size_t)(((kg-half)<<6)+(mh<<5)+cp)*17;
            #pragma unroll
            for(int i=0;i<8;i++){ dst[i]=aC[i]; dst[8+i]=aH[i]; }
          }
          __syncthreads();
          if(kg<half){
            const ull* src = red + (size_t)((kg<<6)+(mh<<5)+cp)*17;
            #pragma unroll
            for(int i=0;i<8;i++){ add2(aC[i],src[i]); add2(aH[i],src[8+i]); }
          }
          __syncthreads();
        }
        if(kg==0){
          #pragma unroll
          for(int i=0;i<8;i++){
            g_pC[unit][ks][mpb+i][col]=aC[i];
            g_pH[unit][ks][mpb+i][col]=aH[i];
          }
        }
        __syncthreads();
      }
      gbar(bar);
      {
        const int pslot = tid>>7;
        const int ppos  = tid&127;
        const int pos   = bid*128 + ppos;
        const int mp=pos>>10, pcol=pos&1023;
        if(pslot<E){
          float o0,o1;
          red_unit(c_lu[L][pslot],mp,pcol,t,o0,o1);
          if(L==4) rbuf[pslot][ppos]=packf(o0,o1);
        }
        if(L==4){
          __syncthreads();
          if(pslot==3){
            const ull va=rbuf[0][ppos], vb=rbuf[1][ppos];
            float h0v=lo2(va)+lo2(vb), h1v=hi2(va)+hi2(vb);
            #pragma unroll
            for(int s=1;s<6;s++){
              const ull v=g_sp[s][mp*NHID+pcol];
              h0v+=lo2(v); h1v+=hi2(v);
            }
            { const ull v=g_sp[7][mp*NHID+pcol]; h0v+=lo2(v); h1v+=hi2(v); }
            h0v*=0.125f; h1v*=0.125f;
            const int m0=2*mp;
            g_hidden[(size_t)t*BATCH*NHID+(size_t)m0*NHID+pcol]=h0v;
            g_hidden[(size_t)t*BATCH*NHID+(size_t)(m0+1)*NHID+pcol]=h1v;
            g_hp[mp*NHID+pcol]=packf(h0v,h1v);
          }
        }
      }
      gbar(bar);
    }
  }
}

// ---------------- embedding gather ----------------
__global__ void k_embed(const int* __restrict__ tok, const float* __restrict__ encW){
  const int tb=blockIdx.x, t=tok[tb];
  const float4* s=reinterpret_cast<const float4*>(encW+(size_t)t*NHID);
  float4* d=reinterpret_cast<float4*>(g_emb+(size_t)tb*NHID);
  d[threadIdx.x]=s[threadIdx.x];
}

// ---------------- xw0: emb @ W0[0:1024,:] (fp32x2, 128x64 tile) -------------
__global__ void k_xw0f(const float* __restrict__ W0){
  __shared__ float As[16][136];
  __shared__ float Bs[16][68];
  const int tid=threadIdx.x;
  const int m0=blockIdx.y*128, n0=blockIdx.x*64;
  const int mg=tid>>4, ng=tid&15;
  const int m0t=mg<<3, n0t=ng<<2;
  ull acc[4][4];
  #pragma unroll
  for(int p=0;p<4;p++)
    #pragma unroll
    for(int n=0;n<4;n++) acc[p][n]=0ull;
  for(int kk0=0;kk0<NHID;kk0+=16){
    #pragma unroll
    for(int it=0;it<2;it++){
      const int li=tid+(it<<8);
      const int r=li>>2, q=(li&3)<<2;
      const float4 v=*reinterpret_cast<const float4*>(&g_emb[(size_t)(m0+r)*NHID+kk0+q]);
      As[q+0][r]=v.x; As[q+1][r]=v.y; As[q+2][r]=v.z; As[q+3][r]=v.w;
    }
    {
      const int r=tid>>4, q=(tid&15)<<2;
      const float4 v=*reinterpret_cast<const float4*>(&W0[(size_t)(kk0+r)*NH2+n0+q]);
      *reinterpret_cast<float4*>(&Bs[r][q])=v;
    }
    __syncthreads();
    #pragma unroll
    for(int kk=0;kk<16;kk++){
      const ulonglong2 a01=*reinterpret_cast<const ulonglong2*>(&As[kk][m0t]);
      const ulonglong2 a23=*reinterpret_cast<const ulonglong2*>(&As[kk][m0t+4]);
      const float4 b=*reinterpret_cast<const float4*>(&Bs[kk][n0t]);
      const ull b0=dupf(b.x), b1=dupf(b.y), b2=dupf(b.z), b3=dupf(b.w);
      fma2(acc[0][0],a01.x,b0); fma2(acc[0][1],a01.x,b1);
      fma2(acc[0][2],a01.x,b2); fma2(acc[0][3],a01.x,b3);
      fma2(acc[1][0],a01.y,b0); fma2(acc[1][1],a01.y,b1);
      fma2(acc[1][2],a01.y,b2); fma2(acc[1][3],a01.y,b3);
      fma2(acc[2][0],a23.x,b0); fma2(acc[2][1],a23.x,b1);
      fma2(acc[2][2],a23.x,b2); fma2(acc[2][3],a23.x,b3);
      fma2(acc[3][0],a23.y,b0); fma2(acc[3][1],a23.y,b1);
      fma2(acc[3][2],a23.y,b2); fma2(acc[3][3],a23.y,b3);
    }
    __syncthreads();
  }
  #pragma unroll
  for(int p=0;p<4;p++){
    const int m=m0+m0t+(p<<1);
    #pragma unroll
    for(int nn=0;nn<4;nn++){
      const int n_=n0+n0t+nn;
      g_xw0[(size_t)m*NH2+n_]    =lo2(acc[p][nn]);
      g_xw0[(size_t)(m+1)*NH2+n_]=hi2(acc[p][nn]);
    }
  }
}

// ---------------- decoder via mma.sync tf32 (m16n8k8) -----------------------
// block 256 thr = 8 warps; tile 128m x 64n; warp w owns rows w*16..w*16+15,
// iterates 8 n-subtiles of 8. A/B staged per 16-k chunk, pre-converted tf32.
__global__ __launch_bounds__(256) void k_decT(const float* __restrict__ encW,
                                              const float* __restrict__ decb,
                                              float* __restrict__ out){
  __shared__ __align__(16) uint32_t As[128*20];   // [m][k], stride 20 (pad)
  __shared__ __align__(16) uint32_t Bs[64*20];    // [n][k], stride 20 (pad)
  const int tid=threadIdx.x;
  const int w=tid>>5, lane=tid&31;
  const int g=lane>>2, c=lane&3;                  // groupID, threadInGroup
  const int m0=blockIdx.y*128, n0=blockIdx.x*64;

  float d[8][4];
  #pragma unroll
  for(int nt=0;nt<8;nt++){ d[nt][0]=0.f; d[nt][1]=0.f; d[nt][2]=0.f; d[nt][3]=0.f; }

  for(int kc=0;kc<NHID;kc+=16){
    // stage A: 128 rows x 16 k (tf32) — 2 float4 per thread, coalesced
    #pragma unroll
    for(int it=0;it<2;it++){
      const int li=tid+(it<<8);
      const int m=li>>2, kq=(li&3)<<2;
      const float4 v=*reinterpret_cast<const float4*>(&g_hidden[(size_t)(m0+m)*NHID+kc+kq]);
      uint4 u; u.x=f2tf(v.x); u.y=f2tf(v.y); u.z=f2tf(v.z); u.w=f2tf(v.w);
      *reinterpret_cast<uint4*>(&As[m*20+kq])=u;
    }
    // stage B: 64 rows (n) x 16 k (tf32) — 1 float4 per thread
    {
      const int n=tid>>2, kq=(tid&3)<<2;
      float4 v=make_float4(0.f,0.f,0.f,0.f);
      if(n0+n<NTOK) v=*reinterpret_cast<const float4*>(&encW[(size_t)(n0+n)*NHID+kc+kq]);
      uint4 u; u.x=f2tf(v.x); u.y=f2tf(v.y); u.z=f2tf(v.z); u.w=f2tf(v.w);
      *reinterpret_cast<uint4*>(&Bs[n*20+kq])=u;
    }
    __syncthreads();
    #pragma unroll
    for(int kk=0;kk<2;kk++){
      const int kb=kk*8;
      const uint32_t a0=As[(w*16+g)*20   + kb + c];
      const uint32_t a1=As[(w*16+g+8)*20 + kb + c];
      const uint32_t a2=As[(w*16+g)*20   + kb + c + 4];
      const uint32_t a3=As[(w*16+g+8)*20 + kb + c + 4];
      #pragma unroll
      for(int nt=0;nt<8;nt++){
        const uint32_t b0=Bs[(nt*8+g)*20 + kb + c];
        const uint32_t b1=Bs[(nt*8+g)*20 + kb + c + 4];
        mma_tf32(d[nt], a0,a1,a2,a3, b0,b1);
      }
    }
    __syncthreads();
  }
  // epilogue: d0=D[g][2c], d1=D[g][2c+1], d2=D[g+8][2c], d3=D[g+8][2c+1]
  #pragma unroll
  for(int nt=0;nt<8;nt++){
    const int n=n0+nt*8+2*c;
    if(n<NTOK){
      const float b0v=decb[n], b1v=decb[n+1];
      const int m=m0+w*16+g;
      float2 r0; r0.x=d[nt][0]+b0v; r0.y=d[nt][1]+b1v;
      float2 r1; r1.x=d[nt][2]+b0v; r1.y=d[nt][3]+b1v;
      *reinterpret_cast<float2*>(&out[(size_t)m*NTOK+n])     = r0;
      *reinterpret_cast<float2*>(&out[(size_t)(m+8)*NTOK+n]) = r1;
    }
  }
}

// ---------------- in-place log_softmax --------------------------------------
__global__ void k_lsm(float* __restrict__ out){
  const int row=blockIdx.x;
  float* p=out+(size_t)row*NTOK;
  __shared__ float red[256];
  float mx=-1e30f;
  for(int i=threadIdx.x;i<NTOK;i+=256) mx=fmaxf(mx,p[i]);
  red[threadIdx.x]=mx; __syncthreads();
  for(int s=128;s>0;s>>=1){
    if(threadIdx.x<s) red[threadIdx.x]=fmaxf(red[threadIdx.x],red[threadIdx.x+s]);
    __syncthreads();
  }
  mx=red[0]; __syncthreads();
  float sum=0.f;
  for(int i=threadIdx.x;i<NTOK;i+=256) sum+=expf(p[i]-mx);
  red[threadIdx.x]=sum; __syncthreads();
  for(int s=128;s>0;s>>=1){
    if(threadIdx.x<s) red[threadIdx.x]+=red[threadIdx.x+s];
    __syncthreads();
  }
  const float lse=mx+logf(red[0]);
  for(int i=threadIdx.x;i<NTOK;i+=256) p[i]=p[i]-lse;
}

__global__ void k_hlast(float* __restrict__ out){
  float4* d=reinterpret_cast<float4*>(out+(size_t)TB*NTOK);
  const float4* s=reinterpret_cast<const float4*>(g_hidden+(size_t)(T_STEPS-1)*BATCH*NHID);
  const int i=blockIdx.x*256+threadIdx.x;
  d[i]=s[i];
}

extern "C" void kernel_launch(void* const* d_in, const int* in_sizes, int n_in,
                              void* d_out, int out_size){
  const int*   tokens=(const int*)  d_in[0];
  const float* h0    =(const float*)d_in[1];
  const float* encW  =(const float*)d_in[2];
  const float* W0    =(const float*)d_in[3];
  const float* Ws    =(const float*)d_in[4];
  const float* decb  =(const float*)d_in[5];
  float* out=(float*)d_out;

  k_embed<<<TB,256>>>(tokens,encW);
  k_pack0<<<64,256>>>(h0);
  k_xw0f<<<dim3(NH2/64,TB/128),256>>>(W0);
  k_rnn<<<NB,NT>>>(W0,Ws);
  k_decT<<<dim3((NTOK+63)/64,TB/128),256>>>(encW,decb,out);
  k_lsm<<<TB,256>>>(out);
  k_hlast<<<(BATCH*NHID/4)/256,256>>>(out);
}